// round 12
// baseline (speedup 1.0000x reference)
#include <cuda_runtime.h>
#include <cuda_bf16.h>
#include <cstdint>

// Problem constants (fixed by setup_inputs)
#define HPM       8
#define NUM_PAGES 4096
#define PAGE_SIZE 16
#define DPM       128
#define MAX_SEQS  8
#define MAX_PPS   256
#define D4        (DPM / 4)                                    // 32 float4 per row
#define PAGES_ELEMS (2LL * HPM * NUM_PAGES * PAGE_SIZE * DPM)  // 134,217,728 floats
#define INNER_F4  (HPM * NUM_PAGES * PAGE_SIZE * D4)           // 1<<24 float4 per tensor
#define TOTAL_F4  (2u * INNER_F4)                              // 1<<25

#define NTHREADS  256
#define NBLOCKS   1184         // 148 SMs x 8 blocks: exactly ONE wave
#define NTILES    (TOTAL_F4 / 1024u)   // 32768 tiles of 1024 f4 (= 2 pages each)

// ---------------------------------------------------------------------------
// Persistent single-wave fused kernel.
//  - All 1184 blocks resident simultaneously (64 warps/SM = R8's MLP regime).
//  - Prologue (once per block, parallel at t=0): scan page_indices, build the
//    FULL 4096-entry page->block table in this block's smem (16KB).
//  - Copy: grid-stride over 32768 tiles; inner body = proven R8 copy body,
//    b0/b1 from 2 broadcast LDS per tile.
//  - Block 0 also emits the two small outputs.
//  No atomics, no flags, no cross-block sync: deterministic & graph-safe.
// ---------------------------------------------------------------------------
__global__ void __launch_bounds__(NTHREADS, 8)
fused_pages_kernel(const float4* __restrict__ key,          // [1, S, H, D]
                   const float4* __restrict__ value,
                   const float4* __restrict__ key_pages,    // [H, P, PS, D]
                   const float4* __restrict__ value_pages,
                   const int*    __restrict__ page_indices,
                   const int*    __restrict__ seq_page_indices,
                   const int*    __restrict__ slot_p,
                   const int*    __restrict__ true_length_p,
                   float4* __restrict__ out,                 // [2, H, P, PS, D]
                   float*  __restrict__ out_pi,              // [4096]
                   float*  __restrict__ out_spi)             // [8, 256]
{
    __shared__ int s_blk[NUM_PAGES];   // page -> block index (-1 = passthrough)
    __shared__ int s_pob[MAX_PPS];     // block -> page (block 0 only)
    __shared__ int s_base[8];

    const int tid  = threadIdx.x;
    const int lane = tid & 31;
    const int wrp  = tid >> 5;
    const unsigned bIdx = blockIdx.x;

    // ---------------- Prologue pass 1: counts ----------------
    const int4* pi4 = (const int4*)page_indices;
    int cnt = 0;
#pragma unroll
    for (int k = 0; k < 4; k++) {
        int4 v = __ldg(&pi4[tid * 4 + k]);
        int bp = tid * 16 + k * 4;
        cnt += (bp >= 1) && (v.x == 0);
        cnt += (v.y == 0);
        cnt += (v.z == 0);
        cnt += (v.w == 0);
    }
    const int tl_in = __ldg(true_length_p);

    // Warp inclusive scan of per-thread counts
    int incl = cnt;
#pragma unroll
    for (int off = 1; off < 32; off <<= 1) {
        int n = __shfl_up_sync(0xffffffffu, incl, off);
        if (lane >= off) incl += n;
    }
    if (lane == 31) s_base[wrp] = incl;
    __syncthreads();

    if (wrp == 0 && lane < 8) {
        int v = s_base[lane];
        int s = v;
#pragma unroll
        for (int off = 1; off < 8; off <<= 1) {
            int n = __shfl_up_sync(0xffu, s, off);
            if (lane >= off) s += n;
        }
        s_base[lane] = s - v;
    }
    __syncthreads();

    int run = s_base[wrp] + (incl - cnt);   // exclusive rank of this thread's first page

    int nb = (tl_in + PAGE_SIZE - 1) / PAGE_SIZE;
    if (nb > MAX_PPS) nb = MAX_PPS;

    // ---------------- Prologue pass 2: fill the table (reload from L2) ----------------
#pragma unroll
    for (int k = 0; k < 4; k++) {
        int4 v = __ldg(&pi4[tid * 4 + k]);
        int pvals[4] = { v.x, v.y, v.z, v.w };
#pragma unroll
        for (int q = 0; q < 4; q++) {
            int p  = tid * 16 + k * 4 + q;
            int fr = (p >= 1) && (pvals[q] == 0);
            int b  = -1;
            if (fr) {
                if (run < nb) {
                    b = run;
                    if (bIdx == 0) s_pob[run] = p;
                }
                run++;
            }
            s_blk[p] = b;
            if (bIdx == 0) out_pi[p] = (b >= 0) ? 1.0f : (float)pvals[q];
        }
    }
    __syncthreads();   // table ready

    // Block 0: seq_page_indices output
    if (bIdx == 0) {
        const int slot = __ldg(slot_p);
#pragma unroll
        for (int k = 0; k < 8; k++) {
            int i = tid + k * 256;
            int r = i >> 8, c = i & 255;
            float v = (float)__ldg(&seq_page_indices[i]);
            if (r == slot && c < nb) v = (float)s_pob[c];
            out_spi[i] = v;
        }
    }

    // ---------------- Copy phase: grid-stride over tiles, R8 body ----------------
    for (unsigned tile = bIdx; tile < NTILES; tile += NBLOCKS) {
        const unsigned t = tile >> 14;                  // 0 = key, 1 = value (warp-uniform)
        const unsigned h = (tile >> 11) & (HPM - 1);    // head (warp-uniform)
        const float4* __restrict__ kv    = t ? value       : key;
        const float4* __restrict__ pages = t ? value_pages : key_pages;

        const unsigned p0 = (2u * tile) & (NUM_PAGES - 1);
        const int b0 = s_blk[p0];                       // broadcast LDS
        const int b1 = s_blk[p0 + 1];

        const unsigned base = tile * 1024u + tid;

        const float4* srcs[4];
#pragma unroll
        for (int j = 0; j < 4; j++) {
            unsigned idx = base + j * 256u;
            unsigned d4  = idx & (D4 - 1);
            unsigned row = (idx >> 5) & (PAGE_SIZE - 1);

            int b = (j < 2) ? b0 : b1;
            unsigned s    = (unsigned)b * PAGE_SIZE + row;
            unsigned offA = (s * HPM + h) * D4 + d4;     // key/value (transpose folded)
            unsigned offB = idx & (INNER_F4 - 1);        // pass-through pages
            srcs[j] = (b >= 0) ? (kv + offA) : (pages + offB);
        }

        float4 v4[4];
#pragma unroll
        for (int j = 0; j < 4; j++) v4[j] = __ldcs(srcs[j]);   // 4 back-to-back LDG.128.CS

#pragma unroll
        for (int j = 0; j < 4; j++) __stcs(&out[base + j * 256u], v4[j]);
    }
}

// ---------------------------------------------------------------------------
// Launch — ONE kernel node, single persistent wave.
// Inputs: key, value, key_pages, value_pages, page_indices, seq_page_indices,
//         slot, true_length
// Output: concat(pages[2,H,P,PS,D], page_indices[4096], seq_page_indices[2048])
// ---------------------------------------------------------------------------
extern "C" void kernel_launch(void* const* d_in, const int* in_sizes, int n_in,
                              void* d_out, int out_size)
{
    const float* key          = (const float*)d_in[0];
    const float* value        = (const float*)d_in[1];
    const float* key_pages    = (const float*)d_in[2];
    const float* value_pages  = (const float*)d_in[3];
    const int*   page_indices = (const int*)d_in[4];
    const int*   seq_page_ind = (const int*)d_in[5];
    const int*   slot         = (const int*)d_in[6];
    const int*   true_length  = (const int*)d_in[7];

    float* out_pages = (float*)d_out;
    float* out_pi    = out_pages + PAGES_ELEMS;
    float* out_spi   = out_pi + NUM_PAGES;

    fused_pages_kernel<<<NBLOCKS, NTHREADS>>>(
        (const float4*)key, (const float4*)value,
        (const float4*)key_pages, (const float4*)value_pages,
        page_indices, seq_page_ind, slot, true_length,
        (float4*)out_pages, out_pi, out_spi);
}

// round 13
// speedup vs baseline: 1.0278x; 1.0278x over previous
#include <cuda_runtime.h>
#include <cuda_bf16.h>
#include <cstdint>

// Problem constants (fixed by setup_inputs)
#define HPM       8
#define NUM_PAGES 4096
#define PAGE_SIZE 16
#define DPM       128
#define MAX_SEQS  8
#define MAX_PPS   256
#define D4        (DPM / 4)                                    // 32 float4 per row
#define PAGES_ELEMS (2LL * HPM * NUM_PAGES * PAGE_SIZE * DPM)  // 134,217,728 floats
#define INNER_F4  (HPM * NUM_PAGES * PAGE_SIZE * D4)           // 1<<24 float4 per tensor
#define TOTAL_F4  (2u * INNER_F4)                              // 1<<25

#define NTHREADS  256
#define NBLOCKS   592                  // 148 SMs x 4 blocks: one wave @ <=64 regs
#define NTILES    (TOTAL_F4 / 1024u)   // 32768 tiles of 1024 f4 (= 2 pages each)

// ---------------------------------------------------------------------------
// Persistent single-wave fused kernel, SOFTWARE-PIPELINED copy loop:
// tile i+1's 4 loads are issued BEFORE tile i's stores, so each warp keeps
// 8 loads in flight across iteration boundaries (R12's serialization fix).
// Prologue per block: build the full 4096-entry page->block table in smem.
// Block 0 also emits the two small outputs. No atomics/flags/cross-block sync.
// ---------------------------------------------------------------------------
__global__ void __launch_bounds__(NTHREADS, 4)
fused_pages_kernel(const float4* __restrict__ key,          // [1, S, H, D]
                   const float4* __restrict__ value,
                   const float4* __restrict__ key_pages,    // [H, P, PS, D]
                   const float4* __restrict__ value_pages,
                   const int*    __restrict__ page_indices,
                   const int*    __restrict__ seq_page_indices,
                   const int*    __restrict__ slot_p,
                   const int*    __restrict__ true_length_p,
                   float4* __restrict__ out,                 // [2, H, P, PS, D]
                   float*  __restrict__ out_pi,              // [4096]
                   float*  __restrict__ out_spi)             // [8, 256]
{
    __shared__ int s_blk[NUM_PAGES];   // page -> block index (-1 = passthrough)
    __shared__ int s_pob[MAX_PPS];     // block -> page (block 0 only)
    __shared__ int s_base[8];

    const int tid  = threadIdx.x;
    const int lane = tid & 31;
    const int wrp  = tid >> 5;
    const unsigned bIdx = blockIdx.x;

    // ---------------- Prologue pass 1: counts ----------------
    const int4* pi4 = (const int4*)page_indices;
    int cnt = 0;
#pragma unroll
    for (int k = 0; k < 4; k++) {
        int4 v = __ldg(&pi4[tid * 4 + k]);
        int bp = tid * 16 + k * 4;
        cnt += (bp >= 1) && (v.x == 0);
        cnt += (v.y == 0);
        cnt += (v.z == 0);
        cnt += (v.w == 0);
    }
    const int tl_in = __ldg(true_length_p);

    int incl = cnt;
#pragma unroll
    for (int off = 1; off < 32; off <<= 1) {
        int n = __shfl_up_sync(0xffffffffu, incl, off);
        if (lane >= off) incl += n;
    }
    if (lane == 31) s_base[wrp] = incl;
    __syncthreads();

    if (wrp == 0 && lane < 8) {
        int v = s_base[lane];
        int s = v;
#pragma unroll
        for (int off = 1; off < 8; off <<= 1) {
            int n = __shfl_up_sync(0xffu, s, off);
            if (lane >= off) s += n;
        }
        s_base[lane] = s - v;
    }
    __syncthreads();

    int run = s_base[wrp] + (incl - cnt);

    int nb = (tl_in + PAGE_SIZE - 1) / PAGE_SIZE;
    if (nb > MAX_PPS) nb = MAX_PPS;

    // ---------------- Prologue pass 2: fill table (reload from L2) ----------------
#pragma unroll
    for (int k = 0; k < 4; k++) {
        int4 v = __ldg(&pi4[tid * 4 + k]);
        int pvals[4] = { v.x, v.y, v.z, v.w };
#pragma unroll
        for (int q = 0; q < 4; q++) {
            int p  = tid * 16 + k * 4 + q;
            int fr = (p >= 1) && (pvals[q] == 0);
            int b  = -1;
            if (fr) {
                if (run < nb) {
                    b = run;
                    if (bIdx == 0) s_pob[run] = p;
                }
                run++;
            }
            s_blk[p] = b;
            if (bIdx == 0) out_pi[p] = (b >= 0) ? 1.0f : (float)pvals[q];
        }
    }
    __syncthreads();

    if (bIdx == 0) {
        const int slot = __ldg(slot_p);
#pragma unroll
        for (int k = 0; k < 8; k++) {
            int i = tid + k * 256;
            int r = i >> 8, c = i & 255;
            float v = (float)__ldg(&seq_page_indices[i]);
            if (r == slot && c < nb) v = (float)s_pob[c];
            out_spi[i] = v;
        }
    }

    // ---------------- Copy phase: pipelined grid-stride ----------------
    // prep(tile): compute the 4 source pointers for this thread's slice.
    auto prep = [&](unsigned tile, const float4** srcs) {
        const unsigned t = tile >> 14;
        const unsigned h = (tile >> 11) & (HPM - 1);
        const float4* __restrict__ kv    = t ? value       : key;
        const float4* __restrict__ pages = t ? value_pages : key_pages;
        const unsigned p0 = (2u * tile) & (NUM_PAGES - 1);
        const int b0 = s_blk[p0];
        const int b1 = s_blk[p0 + 1];
        const unsigned base = tile * 1024u + tid;
#pragma unroll
        for (int j = 0; j < 4; j++) {
            unsigned idx = base + j * 256u;
            unsigned d4  = idx & (D4 - 1);
            unsigned row = (idx >> 5) & (PAGE_SIZE - 1);
            int b = (j < 2) ? b0 : b1;
            unsigned s    = (unsigned)b * PAGE_SIZE + row;
            unsigned offA = (s * HPM + h) * D4 + d4;
            unsigned offB = idx & (INNER_F4 - 1);
            srcs[j] = (b >= 0) ? (kv + offA) : (pages + offB);
        }
    };

    unsigned tileA = bIdx;               // every block has >= 1 tile (32768 >> 592)
    const float4* srcsA[4];
    float4 valsA[4];
    prep(tileA, srcsA);
#pragma unroll
    for (int j = 0; j < 4; j++) valsA[j] = __ldcs(srcsA[j]);

    for (unsigned tileB = tileA + NBLOCKS; tileB < NTILES; tileB += NBLOCKS) {
        const float4* srcsB[4];
        float4 valsB[4];
        prep(tileB, srcsB);
#pragma unroll
        for (int j = 0; j < 4; j++) valsB[j] = __ldcs(srcsB[j]);   // issue BEFORE stores of A

        const unsigned baseA = tileA * 1024u + tid;
#pragma unroll
        for (int j = 0; j < 4; j++) __stcs(&out[baseA + j * 256u], valsA[j]);

#pragma unroll
        for (int j = 0; j < 4; j++) valsA[j] = valsB[j];
        tileA = tileB;
    }

    const unsigned baseA = tileA * 1024u + tid;
#pragma unroll
    for (int j = 0; j < 4; j++) __stcs(&out[baseA + j * 256u], valsA[j]);
}

// ---------------------------------------------------------------------------
// Launch — ONE kernel node, single persistent wave, pipelined.
// Inputs: key, value, key_pages, value_pages, page_indices, seq_page_indices,
//         slot, true_length
// Output: concat(pages[2,H,P,PS,D], page_indices[4096], seq_page_indices[2048])
// ---------------------------------------------------------------------------
extern "C" void kernel_launch(void* const* d_in, const int* in_sizes, int n_in,
                              void* d_out, int out_size)
{
    const float* key          = (const float*)d_in[0];
    const float* value        = (const float*)d_in[1];
    const float* key_pages    = (const float*)d_in[2];
    const float* value_pages  = (const float*)d_in[3];
    const int*   page_indices = (const int*)d_in[4];
    const int*   seq_page_ind = (const int*)d_in[5];
    const int*   slot         = (const int*)d_in[6];
    const int*   true_length  = (const int*)d_in[7];

    float* out_pages = (float*)d_out;
    float* out_pi    = out_pages + PAGES_ELEMS;
    float* out_spi   = out_pi + NUM_PAGES;

    fused_pages_kernel<<<NBLOCKS, NTHREADS>>>(
        (const float4*)key, (const float4*)value,
        (const float4*)key_pages, (const float4*)value_pages,
        page_indices, seq_page_ind, slot, true_length,
        (float4*)out_pages, out_pi, out_spi);
}

// round 14
// speedup vs baseline: 1.1206x; 1.0903x over previous
#include <cuda_runtime.h>
#include <cuda_bf16.h>
#include <cstdint>

// Problem constants (fixed by setup_inputs)
#define HPM       8
#define NUM_PAGES 4096
#define PAGE_SIZE 16
#define DPM       128
#define MAX_SEQS  8
#define MAX_PPS   256
#define D4        (DPM / 4)                                    // 32 float4 per row
#define PAGES_ELEMS (2LL * HPM * NUM_PAGES * PAGE_SIZE * DPM)  // 134,217,728 floats
#define INNER_F4  (HPM * NUM_PAGES * PAGE_SIZE * D4)           // 1<<24 float4 per tensor
#define TOTAL_F4  (2u * INNER_F4)                              // 1<<25

// Scratch (device globals — no allocation allowed)
__device__ int g_blk_of_page[NUM_PAGES];   // -1 => keep old contents, else block index
__device__ int g_page_of_block[MAX_PPS];

// ---------------------------------------------------------------------------
// Kernel A (slim, R8-identical): first-fit allocation + both small outputs.
// All global reads issued up-front so their DRAM trips overlap.
// ---------------------------------------------------------------------------
__global__ void __launch_bounds__(256)
setup_kernel(const int* __restrict__ page_indices,
             const int* __restrict__ seq_page_indices,
             const int* __restrict__ slot_p,
             const int* __restrict__ true_length_p,
             float* __restrict__ out_pi,
             float* __restrict__ out_spi)
{
    __shared__ int s_base[8];
    const int tid  = threadIdx.x;
    const int lane = tid & 31;
    const int wrp  = tid >> 5;

    const int4* pi4  = (const int4*)page_indices;
    const int4* spi4 = (const int4*)seq_page_indices;
    int4 pv[4], sv[2];
#pragma unroll
    for (int k = 0; k < 4; k++) pv[k] = __ldg(&pi4[tid * 4 + k]);
#pragma unroll
    for (int k = 0; k < 2; k++) sv[k] = __ldg(&spi4[tid * 2 + k]);
    const int tl   = __ldg(true_length_p);
    const int slot = __ldg(slot_p);

    int vals[16], fl[16];
    int cnt = 0;
#pragma unroll
    for (int k = 0; k < 4; k++) {
        vals[k*4+0] = pv[k].x; vals[k*4+1] = pv[k].y;
        vals[k*4+2] = pv[k].z; vals[k*4+3] = pv[k].w;
    }
#pragma unroll
    for (int j = 0; j < 16; j++) {
        int p = tid * 16 + j;
        fl[j] = (p >= 1) && (vals[j] == 0);
        cnt += fl[j];
    }

    int incl = cnt;
#pragma unroll
    for (int off = 1; off < 32; off <<= 1) {
        int n = __shfl_up_sync(0xffffffffu, incl, off);
        if (lane >= off) incl += n;
    }
    if (lane == 31) s_base[wrp] = incl;
    __syncthreads();

    if (wrp == 0 && lane < 8) {
        int v = s_base[lane];
        int s = v;
#pragma unroll
        for (int off = 1; off < 8; off <<= 1) {
            int n = __shfl_up_sync(0xffu, s, off);
            if (lane >= off) s += n;
        }
        s_base[lane] = s - v;
    }
    __syncthreads();

    const int excl = s_base[wrp] + (incl - cnt);

    int nb = (tl + PAGE_SIZE - 1) / PAGE_SIZE;
    if (nb > MAX_PPS) nb = MAX_PPS;

    int run = excl;
    float pi_out[16];
#pragma unroll
    for (int j = 0; j < 16; j++) {
        int p = tid * 16 + j;
        int b = -1;
        if (fl[j]) {
            if (run < nb) { b = run; g_page_of_block[run] = p; }
            run++;
        }
        g_blk_of_page[p] = b;
        pi_out[j] = (b >= 0) ? 1.0f : (float)vals[j];
    }

#pragma unroll
    for (int k = 0; k < 4; k++) {
        float4 v = make_float4(pi_out[k*4+0], pi_out[k*4+1], pi_out[k*4+2], pi_out[k*4+3]);
        ((float4*)out_pi)[tid * 4 + k] = v;
    }

    __syncthreads();   // g_page_of_block visible block-wide

    int svals[8] = { sv[0].x, sv[0].y, sv[0].z, sv[0].w,
                     sv[1].x, sv[1].y, sv[1].z, sv[1].w };
#pragma unroll
    for (int j = 0; j < 8; j++) {
        int i = tid * 8 + j;
        int r = i >> 8, c = i & 255;
        float v = (float)svals[j];
        if (r == slot && c < nb) v = (float)g_page_of_block[c];
        out_spi[i] = v;
    }
}

// ---------------------------------------------------------------------------
// Kernel B: assemble [2, H, P, PS, D]. 128-thread blocks, 512 f4/block =
// exactly ONE page: t/h/p/b all block-uniform (one table load, one branch per
// block). Per-thread shape unchanged from the proven R8 body: 4 independent
// LDG.128.CS -> 4 STG.128.CS, then exit. 16 CTAs/SM => deeper CTA-turnover
// pipeline than R8's 8.
// ---------------------------------------------------------------------------
__global__ void __launch_bounds__(128)
assemble_pages_kernel(const float4* __restrict__ key,        // [1, S, H, D]
                      const float4* __restrict__ value,
                      const float4* __restrict__ key_pages,  // [H, P, PS, D]
                      const float4* __restrict__ value_pages,
                      float4* __restrict__ out)               // [2, H, P, PS, D]
{
    const unsigned bIdx = blockIdx.x;                 // < 65536
    const unsigned base = bIdx * 512u + threadIdx.x;  // block covers 512 f4 (one page)

    const unsigned p = bIdx & (NUM_PAGES - 1);        // page   (block-uniform)
    const unsigned h = (bIdx >> 12) & (HPM - 1);      // head   (block-uniform)
    const unsigned t = bIdx >> 15;                    // tensor (block-uniform)

    const float4* __restrict__ kv    = t ? value       : key;
    const float4* __restrict__ pages = t ? value_pages : key_pages;

    const int b = g_blk_of_page[p];                   // one warp-uniform load per block

    const float4* srcs[4];
#pragma unroll
    for (int j = 0; j < 4; j++) {
        unsigned idx = base + j * 128u;
        unsigned d4  = idx & (D4 - 1);
        unsigned row = (idx >> 5) & (PAGE_SIZE - 1);

        unsigned s    = (unsigned)b * PAGE_SIZE + row;
        unsigned offA = (s * HPM + h) * D4 + d4;      // key/value (transpose folded)
        unsigned offB = idx & (INNER_F4 - 1);         // pass-through pages
        srcs[j] = (b >= 0) ? (kv + offA) : (pages + offB);
    }

    float4 vals[4];
#pragma unroll
    for (int j = 0; j < 4; j++) vals[j] = __ldcs(srcs[j]);   // 4 back-to-back LDG.128.CS

#pragma unroll
    for (int j = 0; j < 4; j++) __stcs(&out[base + j * 128u], vals[j]);
}

// ---------------------------------------------------------------------------
// Launch — two plain kernel nodes (R8 structure).
// Inputs: key, value, key_pages, value_pages, page_indices, seq_page_indices,
//         slot, true_length
// Output: concat(pages[2,H,P,PS,D], page_indices[4096], seq_page_indices[2048])
// ---------------------------------------------------------------------------
extern "C" void kernel_launch(void* const* d_in, const int* in_sizes, int n_in,
                              void* d_out, int out_size)
{
    const float* key          = (const float*)d_in[0];
    const float* value        = (const float*)d_in[1];
    const float* key_pages    = (const float*)d_in[2];
    const float* value_pages  = (const float*)d_in[3];
    const int*   page_indices = (const int*)d_in[4];
    const int*   seq_page_ind = (const int*)d_in[5];
    const int*   slot         = (const int*)d_in[6];
    const int*   true_length  = (const int*)d_in[7];

    float* out_pages = (float*)d_out;
    float* out_pi    = out_pages + PAGES_ELEMS;
    float* out_spi   = out_pi + NUM_PAGES;

    setup_kernel<<<1, 256>>>(page_indices, seq_page_ind, slot, true_length,
                             out_pi, out_spi);

    assemble_pages_kernel<<<TOTAL_F4 / 512u, 128>>>(
        (const float4*)key, (const float4*)value,
        (const float4*)key_pages, (const float4*)value_pages,
        (float4*)out_pages);
}

// round 15
// speedup vs baseline: 1.1213x; 1.0006x over previous
#include <cuda_runtime.h>
#include <cuda_bf16.h>
#include <cstdint>

// Problem constants (fixed by setup_inputs)
#define HPM       8
#define NUM_PAGES 4096
#define PAGE_SIZE 16
#define DPM       128
#define MAX_SEQS  8
#define MAX_PPS   256
#define D4        (DPM / 4)                                    // 32 float4 per row
#define PAGES_ELEMS (2LL * HPM * NUM_PAGES * PAGE_SIZE * DPM)  // 134,217,728 floats
#define INNER_F4  (HPM * NUM_PAGES * PAGE_SIZE * D4)           // 1<<24 float4 per tensor
#define TOTAL_F4  (2u * INNER_F4)                              // 1<<25

// Scratch (device global — no allocation allowed)
__device__ int g_blk_of_page[NUM_PAGES];   // -1 => keep old contents, else block index

// ---------------------------------------------------------------------------
// Kernel A: first-fit allocation, TWO independent blocks run concurrently:
//   block 0: scan -> g_blk_of_page table + out_pi
//   block 1: scan -> private page_of_block (smem) -> out_spi
// Wall time = scan + max(tail) instead of scan + sum(tails).
// ---------------------------------------------------------------------------
__global__ void __launch_bounds__(256)
setup_kernel(const int* __restrict__ page_indices,
             const int* __restrict__ seq_page_indices,
             const int* __restrict__ slot_p,
             const int* __restrict__ true_length_p,
             float* __restrict__ out_pi,
             float* __restrict__ out_spi)
{
    __shared__ int s_base[8];
    __shared__ int s_pob[MAX_PPS];     // used by block 1 only
    const int tid  = threadIdx.x;
    const int lane = tid & 31;
    const int wrp  = tid >> 5;
    const unsigned bIdx = blockIdx.x;

    // ---- Shared prologue: load 16 pages/thread, count free ----
    const int4* pi4 = (const int4*)page_indices;
    int4 pv[4];
#pragma unroll
    for (int k = 0; k < 4; k++) pv[k] = __ldg(&pi4[tid * 4 + k]);
    const int tl = __ldg(true_length_p);

    int vals[16], fl[16];
    int cnt = 0;
#pragma unroll
    for (int k = 0; k < 4; k++) {
        vals[k*4+0] = pv[k].x; vals[k*4+1] = pv[k].y;
        vals[k*4+2] = pv[k].z; vals[k*4+3] = pv[k].w;
    }
#pragma unroll
    for (int j = 0; j < 16; j++) {
        int p = tid * 16 + j;
        fl[j] = (p >= 1) && (vals[j] == 0);
        cnt += fl[j];
    }

    // Warp inclusive scan of per-thread counts
    int incl = cnt;
#pragma unroll
    for (int off = 1; off < 32; off <<= 1) {
        int n = __shfl_up_sync(0xffffffffu, incl, off);
        if (lane >= off) incl += n;
    }
    if (lane == 31) s_base[wrp] = incl;
    __syncthreads();

    if (wrp == 0 && lane < 8) {
        int v = s_base[lane];
        int s = v;
#pragma unroll
        for (int off = 1; off < 8; off <<= 1) {
            int n = __shfl_up_sync(0xffu, s, off);
            if (lane >= off) s += n;
        }
        s_base[lane] = s - v;
    }
    __syncthreads();

    int run = s_base[wrp] + (incl - cnt);   // exclusive rank of this thread's first page

    int nb = (tl + PAGE_SIZE - 1) / PAGE_SIZE;
    if (nb > MAX_PPS) nb = MAX_PPS;

    if (bIdx == 0) {
        // ---- Block 0: publish table + out_pi ----
        float pi_out[16];
#pragma unroll
        for (int j = 0; j < 16; j++) {
            int p = tid * 16 + j;
            int b = -1;
            if (fl[j]) {
                if (run < nb) b = run;
                run++;
            }
            g_blk_of_page[p] = b;
            pi_out[j] = (b >= 0) ? 1.0f : (float)vals[j];
        }
#pragma unroll
        for (int k = 0; k < 4; k++) {
            float4 v = make_float4(pi_out[k*4+0], pi_out[k*4+1], pi_out[k*4+2], pi_out[k*4+3]);
            ((float4*)out_pi)[tid * 4 + k] = v;
        }
    } else {
        // ---- Block 1: private page_of_block -> out_spi ----
        const int4* spi4 = (const int4*)seq_page_indices;
        int4 sv[2];
#pragma unroll
        for (int k = 0; k < 2; k++) sv[k] = __ldg(&spi4[tid * 2 + k]);
        const int slot = __ldg(slot_p);

#pragma unroll
        for (int j = 0; j < 16; j++) {
            int p = tid * 16 + j;
            if (fl[j]) {
                if (run < nb) s_pob[run] = p;
                run++;
            }
        }
        __syncthreads();   // s_pob ready

        int svals[8] = { sv[0].x, sv[0].y, sv[0].z, sv[0].w,
                         sv[1].x, sv[1].y, sv[1].z, sv[1].w };
#pragma unroll
        for (int j = 0; j < 8; j++) {
            int i = tid * 8 + j;
            int r = i >> 8, c = i & 255;
            float v = (float)svals[j];
            if (r == slot && c < nb) v = (float)s_pob[c];
            out_spi[i] = v;
        }
    }
}

// ---------------------------------------------------------------------------
// Kernel B: assemble [2, H, P, PS, D] — R14 body, UNCHANGED (150.9us,
// DRAM 85.3%, regs 22). 128-thread blocks, one page per block: t/h/p/b all
// block-uniform; 4 independent LDG.128.CS -> 4 STG.128.CS, then exit.
// ---------------------------------------------------------------------------
__global__ void __launch_bounds__(128)
assemble_pages_kernel(const float4* __restrict__ key,        // [1, S, H, D]
                      const float4* __restrict__ value,
                      const float4* __restrict__ key_pages,  // [H, P, PS, D]
                      const float4* __restrict__ value_pages,
                      float4* __restrict__ out)               // [2, H, P, PS, D]
{
    const unsigned bIdx = blockIdx.x;                 // < 65536
    const unsigned base = bIdx * 512u + threadIdx.x;  // block covers 512 f4 (one page)

    const unsigned p = bIdx & (NUM_PAGES - 1);        // page   (block-uniform)
    const unsigned h = (bIdx >> 12) & (HPM - 1);      // head   (block-uniform)
    const unsigned t = bIdx >> 15;                    // tensor (block-uniform)

    const float4* __restrict__ kv    = t ? value       : key;
    const float4* __restrict__ pages = t ? value_pages : key_pages;

    const int b = g_blk_of_page[p];                   // one warp-uniform load per block

    const float4* srcs[4];
#pragma unroll
    for (int j = 0; j < 4; j++) {
        unsigned idx = base + j * 128u;
        unsigned d4  = idx & (D4 - 1);
        unsigned row = (idx >> 5) & (PAGE_SIZE - 1);

        unsigned s    = (unsigned)b * PAGE_SIZE + row;
        unsigned offA = (s * HPM + h) * D4 + d4;      // key/value (transpose folded)
        unsigned offB = idx & (INNER_F4 - 1);         // pass-through pages
        srcs[j] = (b >= 0) ? (kv + offA) : (pages + offB);
    }

    float4 vals[4];
#pragma unroll
    for (int j = 0; j < 4; j++) vals[j] = __ldcs(srcs[j]);   // 4 back-to-back LDG.128.CS

#pragma unroll
    for (int j = 0; j < 4; j++) __stcs(&out[base + j * 128u], vals[j]);
}

// ---------------------------------------------------------------------------
// Launch — two plain kernel nodes.
// Inputs: key, value, key_pages, value_pages, page_indices, seq_page_indices,
//         slot, true_length
// Output: concat(pages[2,H,P,PS,D], page_indices[4096], seq_page_indices[2048])
// ---------------------------------------------------------------------------
extern "C" void kernel_launch(void* const* d_in, const int* in_sizes, int n_in,
                              void* d_out, int out_size)
{
    const float* key          = (const float*)d_in[0];
    const float* value        = (const float*)d_in[1];
    const float* key_pages    = (const float*)d_in[2];
    const float* value_pages  = (const float*)d_in[3];
    const int*   page_indices = (const int*)d_in[4];
    const int*   seq_page_ind = (const int*)d_in[5];
    const int*   slot         = (const int*)d_in[6];
    const int*   true_length  = (const int*)d_in[7];

    float* out_pages = (float*)d_out;
    float* out_pi    = out_pages + PAGES_ELEMS;
    float* out_spi   = out_pi + NUM_PAGES;

    setup_kernel<<<2, 256>>>(page_indices, seq_page_ind, slot, true_length,
                             out_pi, out_spi);

    assemble_pages_kernel<<<TOTAL_F4 / 512u, 128>>>(
        (const float4*)key, (const float4*)value,
        (const float4*)key_pages, (const float4*)value_pages,
        (float4*)out_pages);
}